// round 5
// baseline (speedup 1.0000x reference)
#include <cuda_runtime.h>
#include <cuda_bf16.h>
#include <cstdint>

// Problem constants (shapes fixed by the dataset; sizes re-derived from in_sizes)
#define MAX_NODES 100000
#define IN_DIM    64
#define HID_DIM   32

// Scratch (allocation-free rule: __device__ globals)
__device__ int   g_deg_out[MAX_NODES];
__device__ int   g_deg_in [MAX_NODES];
__device__ float g_h      [MAX_NODES * HID_DIM];   // (X@W) * norm_src

// ---------------------------------------------------------------------------
// K0: zero output accumulator (d_out is poisoned) + degree counters
// ---------------------------------------------------------------------------
__global__ void k_zero(float4* __restrict__ out4, int n) {
    int tot4 = n * (HID_DIM / 4);   // n*8 float4s
    int stride = gridDim.x * blockDim.x;
    for (int i = blockIdx.x * blockDim.x + threadIdx.x; i < tot4; i += stride) {
        out4[i] = make_float4(0.f, 0.f, 0.f, 0.f);
        if (i < n) { g_deg_out[i] = 0; g_deg_in[i] = 0; }
    }
}

// ---------------------------------------------------------------------------
// K1: degree counts (int RED)
// ---------------------------------------------------------------------------
__global__ void k_degrees(const int* __restrict__ src, const int* __restrict__ dst, int E) {
    int stride = gridDim.x * blockDim.x;
    for (int i = blockIdx.x * blockDim.x + threadIdx.x; i < E; i += stride) {
        atomicAdd(&g_deg_out[__ldg(src + i)], 1);
        atomicAdd(&g_deg_in [__ldg(dst + i)], 1);
    }
}

// ---------------------------------------------------------------------------
// K2: h = (X @ W) * rsqrt(max(deg_out,1))
//     One row per thread; W staged in smem (all-thread broadcast reads).
// ---------------------------------------------------------------------------
__global__ void k_gemm_norm(const float* __restrict__ X,
                            const float* __restrict__ W,
                            int n) {
    __shared__ float sW[IN_DIM * HID_DIM];   // 8 KB
    for (int i = threadIdx.x; i < IN_DIM * HID_DIM; i += blockDim.x)
        sW[i] = W[i];
    __syncthreads();

    int r = blockIdx.x * blockDim.x + threadIdx.x;
    if (r >= n) return;

    float acc[HID_DIM];
#pragma unroll
    for (int j = 0; j < HID_DIM; j++) acc[j] = 0.f;

    const float4* xr = reinterpret_cast<const float4*>(X + (size_t)r * IN_DIM);
#pragma unroll 4
    for (int k4 = 0; k4 < IN_DIM / 4; k4++) {
        float4 x = __ldg(xr + k4);
        int k = k4 * 4;
#pragma unroll
        for (int j = 0; j < HID_DIM; j++) {
            acc[j] = fmaf(x.x, sW[(k + 0) * HID_DIM + j],
                     fmaf(x.y, sW[(k + 1) * HID_DIM + j],
                     fmaf(x.z, sW[(k + 2) * HID_DIM + j],
                     fmaf(x.w, sW[(k + 3) * HID_DIM + j], acc[j]))));
        }
    }

    float nrm = rsqrtf(fmaxf((float)g_deg_out[r], 1.0f));
    float4* hr = reinterpret_cast<float4*>(g_h + (size_t)r * HID_DIM);
#pragma unroll
    for (int j4 = 0; j4 < HID_DIM / 4; j4++) {
        float4 v;
        v.x = acc[j4 * 4 + 0] * nrm;
        v.y = acc[j4 * 4 + 1] * nrm;
        v.z = acc[j4 * 4 + 2] * nrm;
        v.w = acc[j4 * 4 + 3] * nrm;
        hr[j4] = v;
    }
}

// ---------------------------------------------------------------------------
// K3: scatter  out[dst] += h[src]
//     8 threads / edge, one float4 each: coalesced 128B gather,
//     vector red.global.add.v4.f32 (4x fewer LSU red ops vs scalar atomicAdd).
// ---------------------------------------------------------------------------
__global__ void k_scatter(const int* __restrict__ src,
                          const int* __restrict__ dst,
                          float* __restrict__ out,
                          int E) {
    long long tid = (long long)blockIdx.x * blockDim.x + threadIdx.x;
    int e = (int)(tid >> 3);
    if (e >= E) return;
    int p = (int)(tid & 7);

    int s = __ldg(src + e);
    int d = __ldg(dst + e);

    float4 v = __ldg(reinterpret_cast<const float4*>(g_h + (size_t)s * HID_DIM) + p);
    float* addr = out + (size_t)d * HID_DIM + p * 4;

    asm volatile("red.global.add.v4.f32 [%0], {%1, %2, %3, %4};"
                 :: "l"(addr), "f"(v.x), "f"(v.y), "f"(v.z), "f"(v.w)
                 : "memory");
}

// ---------------------------------------------------------------------------
// K4: out = relu(out * rsqrt(max(deg_in,1)) + b)   (in place, vectorized)
// ---------------------------------------------------------------------------
__global__ void k_finalize(float4* __restrict__ out4,
                           const float* __restrict__ b,
                           int n) {
    __shared__ float4 sb[HID_DIM / 4];
    if (threadIdx.x < HID_DIM / 4)
        sb[threadIdx.x] = reinterpret_cast<const float4*>(b)[threadIdx.x];
    __syncthreads();

    int tot4 = n * (HID_DIM / 4);
    int i = blockIdx.x * blockDim.x + threadIdx.x;
    if (i >= tot4) return;

    int row = i >> 3;
    int j4  = i & 7;
    float nrm = rsqrtf(fmaxf((float)g_deg_in[row], 1.0f));
    float4 v  = out4[i];
    float4 bb = sb[j4];
    v.x = fmaxf(v.x * nrm + bb.x, 0.f);
    v.y = fmaxf(v.y * nrm + bb.y, 0.f);
    v.z = fmaxf(v.z * nrm + bb.z, 0.f);
    v.w = fmaxf(v.w * nrm + bb.w, 0.f);
    out4[i] = v;
}

// ---------------------------------------------------------------------------
extern "C" void kernel_launch(void* const* d_in, const int* in_sizes, int n_in,
                              void* d_out, int out_size) {
    const float* features = (const float*)d_in[0];
    const int*   src      = (const int*)  d_in[1];
    const int*   dst      = (const int*)  d_in[2];
    const float* W        = (const float*)d_in[3];
    const float* b        = (const float*)d_in[4];
    float*       out      = (float*)d_out;

    int n = in_sizes[0] / IN_DIM;   // 100000
    int E = in_sizes[1];            // 1600000

    const int B = 256;

    // K0: zero out + degrees (grid-stride)
    int tot4 = n * (HID_DIM / 4);
    int g0 = (tot4 + B - 1) / B;
    if (g0 > 2048) g0 = 2048;
    k_zero<<<g0, B>>>((float4*)out, n);

    // K1: degrees
    int g1 = (E + B - 1) / B;
    if (g1 > 4096) g1 = 4096;
    k_degrees<<<g1, B>>>(src, dst, E);

    // K2: gemm + src-norm
    int g2 = (n + B - 1) / B;
    k_gemm_norm<<<g2, B>>>(features, W, n);

    // K3: scatter (8 threads per edge)
    long long threads3 = (long long)E * 8;
    int g3 = (int)((threads3 + B - 1) / B);
    k_scatter<<<g3, B>>>(src, dst, out, E);

    // K4: finalize
    int g4 = (tot4 + B - 1) / B;
    k_finalize<<<g4, B>>>((float4*)out, b, n);
}